// round 8
// baseline (speedup 1.0000x reference)
#include <cuda_runtime.h>
#include <cuda_fp16.h>

#define MAXN 100000
#define MAXE 1600000
#define CAP  128

typedef unsigned long long ull;

// ---- scratch (device globals; no allocation allowed) ----
__device__ int    g_cnt[MAXN];                    // true in-degree (excl. self loop)
__device__ float  g_dinv[MAXN];
__device__ int    g_bkt[(size_t)MAXN * CAP];      // per-dst src buckets (51.2MB)
__device__ __half g_h1[(size_t)MAXN * 64];        // X@W1  (fp16 storage)
__device__ float  g_h2[(size_t)MAXN * 64];        // relu layer-1 output (fp32)
__device__ __half g_h3[(size_t)MAXN * 40];        // h2@W2 (fp16 storage)

// packed f32x2 FMA: d = a*b + d
#define FMA2(d, a, b) asm("fma.rn.f32x2 %0, %1, %2, %0;" : "+l"(d) : "l"(a), "l"(b))
#define PACK2(out, lo, hi) asm("mov.b64 %0, {%1, %2};" : "=l"(out) : "f"(lo), "f"(hi))
#define UNPACK2(lo, hi, in) asm("mov.b64 {%0, %1}, %2;" : "=f"(lo), "=f"(hi) : "l"(in))

struct __align__(8) H4 { __half2 a, b; };

// ---------------- bucket build (replaces CSR scan pipeline) ----------------
__global__ void bucket_k(const int* __restrict__ ei, int E, int N) {
    int i = blockIdx.x * blockDim.x + threadIdx.x;
    if (i >= E) return;
    int s = ei[i];
    int d = ei[E + i];
    if ((unsigned)s >= (unsigned)N || (unsigned)d >= (unsigned)N) return;
    int pos = atomicAdd(g_cnt + d, 1);
    if (pos < CAP) g_bkt[(size_t)d * CAP + pos] = s;
}

__global__ void dinv_k(int N) {
    int i = blockIdx.x * blockDim.x + threadIdx.x;
    if (i < N) g_dinv[i] = rsqrtf((float)g_cnt[i] + 1.0f);  // +1 self loop
}

// ---------------- GEMM layer 1: g_h1 = fp16(X @ W1) ----------------
__global__ __launch_bounds__(256) void gemm1_k(
    const float* __restrict__ X, const float* __restrict__ W, int N)
{
    __shared__ __align__(16) float Ws[128 * 64];
    for (int i = threadIdx.x; i < 128 * 64; i += 256) Ws[i] = W[i];
    __syncthreads();

    int r = blockIdx.x * 256 + threadIdx.x;
    if (r >= N) return;

    ull acc[32];
#pragma unroll
    for (int j = 0; j < 32; j++) acc[j] = 0ULL;

    const float4* xr = (const float4*)(X + (size_t)r * 128);
#pragma unroll 1
    for (int k4 = 0; k4 < 32; k4++) {
        float4 xv = xr[k4];
        ull xa, xb, xc, xd;
        PACK2(xa, xv.x, xv.x); PACK2(xb, xv.y, xv.y);
        PACK2(xc, xv.z, xv.z); PACK2(xd, xv.w, xv.w);
        const ulonglong2* w0 = (const ulonglong2*)(Ws + (k4 * 4 + 0) * 64);
        const ulonglong2* w1 = (const ulonglong2*)(Ws + (k4 * 4 + 1) * 64);
        const ulonglong2* w2 = (const ulonglong2*)(Ws + (k4 * 4 + 2) * 64);
        const ulonglong2* w3 = (const ulonglong2*)(Ws + (k4 * 4 + 3) * 64);
#pragma unroll
        for (int j = 0; j < 16; j++) {
            ulonglong2 a0 = w0[j]; FMA2(acc[2*j], xa, a0.x); FMA2(acc[2*j+1], xa, a0.y);
            ulonglong2 a1 = w1[j]; FMA2(acc[2*j], xb, a1.x); FMA2(acc[2*j+1], xb, a1.y);
            ulonglong2 a2 = w2[j]; FMA2(acc[2*j], xc, a2.x); FMA2(acc[2*j+1], xc, a2.y);
            ulonglong2 a3 = w3[j]; FMA2(acc[2*j], xd, a3.x); FMA2(acc[2*j+1], xd, a3.y);
        }
    }

    __half2 hh[32];
#pragma unroll
    for (int j = 0; j < 32; j++) {
        float lo, hi;
        UNPACK2(lo, hi, acc[j]);
        hh[j] = __floats2half2_rn(lo, hi);
    }
    uint4* Hp = (uint4*)(g_h1 + (size_t)r * 64);
    const uint4* sp = (const uint4*)hh;
#pragma unroll
    for (int j = 0; j < 8; j++) Hp[j] = sp[j];
}

// -------- gather layer 1: h2 = relu( sum_in h1[s]*dinv[s]*dinv[n] + h1[n]*dinv^2 + b1 )
// one warp per node; half-warps alternate edges; lane owns 4 feats (8B fp16)
__global__ __launch_bounds__(256) void gather1_k(const float* __restrict__ b1, int N)
{
    int wid = (blockIdx.x * 256 + threadIdx.x) >> 5;
    int lane = threadIdx.x & 31;
    if (wid >= N) return;
    int n = wid;
    int half = lane >> 4;
    int hl = lane & 15;

    int deg = min(g_cnt[n], CAP);
    const int* bp = g_bkt + (size_t)n * CAP;
    float dn = g_dinv[n];

    float4 acc = make_float4(0.f, 0.f, 0.f, 0.f);
    int e = half;
    for (; e + 2 < deg; e += 4) {
        int s0 = __ldg(bp + e), s1 = __ldg(bp + e + 2);
        float w0 = __ldg(g_dinv + s0) * dn;
        float w1 = __ldg(g_dinv + s1) * dn;
        H4 v0 = *(const H4*)(g_h1 + (size_t)s0 * 64 + hl * 4);
        H4 v1 = *(const H4*)(g_h1 + (size_t)s1 * 64 + hl * 4);
        float2 f0a = __half22float2(v0.a), f0b = __half22float2(v0.b);
        float2 f1a = __half22float2(v1.a), f1b = __half22float2(v1.b);
        acc.x += f0a.x * w0 + f1a.x * w1;
        acc.y += f0a.y * w0 + f1a.y * w1;
        acc.z += f0b.x * w0 + f1b.x * w1;
        acc.w += f0b.y * w0 + f1b.y * w1;
    }
    if (e < deg) {
        int s0 = __ldg(bp + e);
        float w0 = __ldg(g_dinv + s0) * dn;
        H4 v0 = *(const H4*)(g_h1 + (size_t)s0 * 64 + hl * 4);
        float2 f0a = __half22float2(v0.a), f0b = __half22float2(v0.b);
        acc.x += f0a.x * w0; acc.y += f0a.y * w0;
        acc.z += f0b.x * w0; acc.w += f0b.y * w0;
    }

    acc.x += __shfl_xor_sync(0xFFFFFFFFu, acc.x, 16);
    acc.y += __shfl_xor_sync(0xFFFFFFFFu, acc.y, 16);
    acc.z += __shfl_xor_sync(0xFFFFFFFFu, acc.z, 16);
    acc.w += __shfl_xor_sync(0xFFFFFFFFu, acc.w, 16);

    if (half == 0) {
        float sl = dn * dn;
        H4 hv = *(const H4*)(g_h1 + (size_t)n * 64 + hl * 4);
        float2 ha = __half22float2(hv.a), hb = __half22float2(hv.b);
        float4 bb = *(const float4*)(b1 + hl * 4);
        float4 o;
        o.x = fmaxf(acc.x + ha.x * sl + bb.x, 0.f);
        o.y = fmaxf(acc.y + ha.y * sl + bb.y, 0.f);
        o.z = fmaxf(acc.z + hb.x * sl + bb.z, 0.f);
        o.w = fmaxf(acc.w + hb.y * sl + bb.w, 0.f);
        *(float4*)(g_h2 + (size_t)n * 64 + hl * 4) = o;
    }
}

// ---------------- GEMM layer 2: g_h3 = fp16(h2 @ W2) ----------------
__global__ __launch_bounds__(256) void gemm2_k(const float* __restrict__ W, int N)
{
    __shared__ __align__(16) float Ws[64 * 40];
    for (int i = threadIdx.x; i < 64 * 40; i += 256) Ws[i] = W[i];
    __syncthreads();

    int r = blockIdx.x * 256 + threadIdx.x;
    if (r >= N) return;

    ull acc[20];
#pragma unroll
    for (int j = 0; j < 20; j++) acc[j] = 0ULL;

    const float4* xr = (const float4*)(g_h2 + (size_t)r * 64);
#pragma unroll 1
    for (int k4 = 0; k4 < 16; k4++) {
        float4 xv = xr[k4];
        ull xa, xb, xc, xd;
        PACK2(xa, xv.x, xv.x); PACK2(xb, xv.y, xv.y);
        PACK2(xc, xv.z, xv.z); PACK2(xd, xv.w, xv.w);
        const ulonglong2* w0 = (const ulonglong2*)(Ws + (k4 * 4 + 0) * 40);
        const ulonglong2* w1 = (const ulonglong2*)(Ws + (k4 * 4 + 1) * 40);
        const ulonglong2* w2 = (const ulonglong2*)(Ws + (k4 * 4 + 2) * 40);
        const ulonglong2* w3 = (const ulonglong2*)(Ws + (k4 * 4 + 3) * 40);
#pragma unroll
        for (int j = 0; j < 10; j++) {
            ulonglong2 a0 = w0[j]; FMA2(acc[2*j], xa, a0.x); FMA2(acc[2*j+1], xa, a0.y);
            ulonglong2 a1 = w1[j]; FMA2(acc[2*j], xb, a1.x); FMA2(acc[2*j+1], xb, a1.y);
            ulonglong2 a2 = w2[j]; FMA2(acc[2*j], xc, a2.x); FMA2(acc[2*j+1], xc, a2.y);
            ulonglong2 a3 = w3[j]; FMA2(acc[2*j], xd, a3.x); FMA2(acc[2*j+1], xd, a3.y);
        }
    }

    __half2 hh[20];
#pragma unroll
    for (int j = 0; j < 20; j++) {
        float lo, hi;
        UNPACK2(lo, hi, acc[j]);
        hh[j] = __floats2half2_rn(lo, hi);
    }
    uint4* Hp = (uint4*)(g_h3 + (size_t)r * 40);   // 80B row, 16B-aligned
    const uint4* sp = (const uint4*)hh;
#pragma unroll
    for (int j = 0; j < 5; j++) Hp[j] = sp[j];
}

// -------- gather layer 2 + bias + log_softmax --------
// one warp per node; lanes 0..19 own features [2*lane, 2*lane+1] of 40
__global__ __launch_bounds__(256) void gather2_k(float* __restrict__ out,
                                                 const float* __restrict__ b2, int N)
{
    int wid = (blockIdx.x * 256 + threadIdx.x) >> 5;
    int lane = threadIdx.x & 31;
    if (wid >= N) return;
    int n = wid;
    bool act = lane < 20;
    int fo = act ? lane * 2 : 0;

    int deg = min(g_cnt[n], CAP);
    const int* bp = g_bkt + (size_t)n * CAP;
    float dn = g_dinv[n];

    float2 a0 = make_float2(0.f, 0.f), a1 = make_float2(0.f, 0.f);
    float2 a2 = make_float2(0.f, 0.f), a3 = make_float2(0.f, 0.f);
    int e = 0;
    for (; e + 3 < deg; e += 4) {
        int s0 = __ldg(bp + e),     s1 = __ldg(bp + e + 1);
        int s2 = __ldg(bp + e + 2), s3 = __ldg(bp + e + 3);
        float w0 = __ldg(g_dinv + s0) * dn, w1 = __ldg(g_dinv + s1) * dn;
        float w2 = __ldg(g_dinv + s2) * dn, w3 = __ldg(g_dinv + s3) * dn;
        float2 v0 = __half22float2(*(const __half2*)(g_h3 + (size_t)s0 * 40 + fo));
        float2 v1 = __half22float2(*(const __half2*)(g_h3 + (size_t)s1 * 40 + fo));
        float2 v2 = __half22float2(*(const __half2*)(g_h3 + (size_t)s2 * 40 + fo));
        float2 v3 = __half22float2(*(const __half2*)(g_h3 + (size_t)s3 * 40 + fo));
        a0.x += v0.x * w0; a0.y += v0.y * w0;
        a1.x += v1.x * w1; a1.y += v1.y * w1;
        a2.x += v2.x * w2; a2.y += v2.y * w2;
        a3.x += v3.x * w3; a3.y += v3.y * w3;
    }
    for (; e < deg; e++) {
        int s0 = __ldg(bp + e);
        float w0 = __ldg(g_dinv + s0) * dn;
        float2 v0 = __half22float2(*(const __half2*)(g_h3 + (size_t)s0 * 40 + fo));
        a0.x += v0.x * w0; a0.y += v0.y * w0;
    }

    float sl = dn * dn;
    float2 h = __half22float2(*(const __half2*)(g_h3 + (size_t)n * 40 + fo));
    float2 bb = *(const float2*)(b2 + fo);
    float vx = a0.x + a1.x + a2.x + a3.x + h.x * sl + bb.x;
    float vy = a0.y + a1.y + a2.y + a3.y + h.y * sl + bb.y;

    float m = act ? fmaxf(vx, vy) : -3.0e38f;
#pragma unroll
    for (int o = 16; o > 0; o >>= 1) m = fmaxf(m, __shfl_xor_sync(0xFFFFFFFFu, m, o));
    float s = act ? (expf(vx - m) + expf(vy - m)) : 0.f;
#pragma unroll
    for (int o = 16; o > 0; o >>= 1) s += __shfl_xor_sync(0xFFFFFFFFu, s, o);
    float lse = m + logf(s);

    if (act)
        *(float2*)(out + (size_t)n * 40 + fo) = make_float2(vx - lse, vy - lse);
}

extern "C" void kernel_launch(void* const* d_in, const int* in_sizes, int n_in,
                              void* d_out, int out_size)
{
    const float* x  = (const float*)d_in[0];
    const int*   ei = (const int*)d_in[1];      // int32 (JAX x64 disabled)
    const float* W1 = (const float*)d_in[2];
    const float* b1 = (const float*)d_in[3];
    const float* W2 = (const float*)d_in[4];
    const float* b2 = (const float*)d_in[5];
    float* out = (float*)d_out;

    int N = in_sizes[0] / 128;
    int E = in_sizes[1] / 2;
    const int T = 256;

    // bucket build
    void* cnt_ptr = 0;
    cudaGetSymbolAddress(&cnt_ptr, g_cnt);
    cudaMemsetAsync(cnt_ptr, 0, (size_t)N * sizeof(int));
    bucket_k<<<(E + T - 1) / T, T>>>(ei, E, N);
    dinv_k<<<(N + T - 1) / T, T>>>(N);

    // layer 1
    gemm1_k<<<(N + T - 1) / T, T>>>(x, W1, N);
    gather1_k<<<(N * 32 + T - 1) / T, T>>>(b1, N);

    // layer 2
    gemm2_k<<<(N + T - 1) / T, T>>>(W2, N);
    gather2_k<<<(N * 32 + T - 1) / T, T>>>(out, b2, N);
}

// round 9
// speedup vs baseline: 1.4069x; 1.4069x over previous
#include <cuda_runtime.h>

#define MAXN 100000
#define MAXE 1600000
#define CAP  128

typedef unsigned long long ull;

// ---- scratch (device globals; no allocation allowed) ----
__device__ int    g_cnt[MAXN];                    // in-degree (excl. self loop)
__device__ float  g_dinv[MAXN];
__device__ int    g_bkt[(size_t)MAXN * CAP];      // per-dst src buckets (51.2MB)
__device__ float  g_h1[(size_t)MAXN * 64];        // X@W1 (fp32)
__device__ float  g_h2[(size_t)MAXN * 64];        // relu layer-1 output
__device__ float  g_h3[(size_t)MAXN * 40];        // h2@W2 (fp32)

// packed f32x2 FMA: d = a*b + d
#define FMA2(d, a, b) asm("fma.rn.f32x2 %0, %1, %2, %0;" : "+l"(d) : "l"(a), "l"(b))
#define PACK2(out, lo, hi) asm("mov.b64 %0, {%1, %2};" : "=l"(out) : "f"(lo), "f"(hi))

// ---------------- bucket build ----------------
__global__ void bucket_k(const int* __restrict__ ei, int E, int N) {
    int i = blockIdx.x * blockDim.x + threadIdx.x;
    if (i >= E) return;
    int s = ei[i];
    int d = ei[E + i];
    if ((unsigned)s >= (unsigned)N || (unsigned)d >= (unsigned)N) return;
    int pos = atomicAdd(g_cnt + d, 1);
    if (pos < CAP) g_bkt[(size_t)d * CAP + pos] = s;
}

__global__ void dinv_k(int N) {
    int i = blockIdx.x * blockDim.x + threadIdx.x;
    if (i < N) g_dinv[i] = rsqrtf((float)g_cnt[i] + 1.0f);  // +1 self loop
}

// ---------------- GEMM layer 1: g_h1 = X @ W1 (f32x2 packed) ----------------
__global__ __launch_bounds__(256) void gemm1_k(
    const float* __restrict__ X, const float* __restrict__ W, int N)
{
    __shared__ __align__(16) float Ws[128 * 64];
    for (int i = threadIdx.x; i < 128 * 64; i += 256) Ws[i] = W[i];
    __syncthreads();

    int r = blockIdx.x * 256 + threadIdx.x;
    if (r >= N) return;

    ull acc[32];
#pragma unroll
    for (int j = 0; j < 32; j++) acc[j] = 0ULL;

    const float4* xr = (const float4*)(X + (size_t)r * 128);
#pragma unroll 1
    for (int k4 = 0; k4 < 32; k4++) {
        float4 xv = xr[k4];
        ull xa, xb, xc, xd;
        PACK2(xa, xv.x, xv.x); PACK2(xb, xv.y, xv.y);
        PACK2(xc, xv.z, xv.z); PACK2(xd, xv.w, xv.w);
        const ulonglong2* w0 = (const ulonglong2*)(Ws + (k4 * 4 + 0) * 64);
        const ulonglong2* w1 = (const ulonglong2*)(Ws + (k4 * 4 + 1) * 64);
        const ulonglong2* w2 = (const ulonglong2*)(Ws + (k4 * 4 + 2) * 64);
        const ulonglong2* w3 = (const ulonglong2*)(Ws + (k4 * 4 + 3) * 64);
#pragma unroll
        for (int j = 0; j < 16; j++) {
            ulonglong2 a0 = w0[j]; FMA2(acc[2*j], xa, a0.x); FMA2(acc[2*j+1], xa, a0.y);
            ulonglong2 a1 = w1[j]; FMA2(acc[2*j], xb, a1.x); FMA2(acc[2*j+1], xb, a1.y);
            ulonglong2 a2 = w2[j]; FMA2(acc[2*j], xc, a2.x); FMA2(acc[2*j+1], xc, a2.y);
            ulonglong2 a3 = w3[j]; FMA2(acc[2*j], xd, a3.x); FMA2(acc[2*j+1], xd, a3.y);
        }
    }

    ulonglong2* Hp = (ulonglong2*)(g_h1 + (size_t)r * 64);
#pragma unroll
    for (int j = 0; j < 16; j++) {
        ulonglong2 v; v.x = acc[2*j]; v.y = acc[2*j+1];
        Hp[j] = v;
    }
}

// -------- gather layer 1: h2 = relu( sum_in h1[s]*dinv[s]*dinv[n] + h1[n]*dinv^2 + b1 )
// one warp per node; half-warps alternate edges (unroll 4); lane owns 4 fp32 feats
__global__ __launch_bounds__(256) void gather1_k(const float* __restrict__ b1, int N)
{
    int wid = (blockIdx.x * 256 + threadIdx.x) >> 5;
    int lane = threadIdx.x & 31;
    if (wid >= N) return;
    int n = wid;
    int half = lane >> 4;
    int hl = lane & 15;

    int deg = min(g_cnt[n], CAP);
    const int* bp = g_bkt + (size_t)n * CAP;
    float dn = g_dinv[n];

    float4 acc = make_float4(0.f, 0.f, 0.f, 0.f);
    int e = half;
    // 4 edges per half per iteration -> 8 loads in flight per warp
    for (; e + 6 < deg; e += 8) {
        int s0 = __ldg(bp + e),     s1 = __ldg(bp + e + 2);
        int s2 = __ldg(bp + e + 4), s3 = __ldg(bp + e + 6);
        float w0 = __ldg(g_dinv + s0) * dn, w1 = __ldg(g_dinv + s1) * dn;
        float w2 = __ldg(g_dinv + s2) * dn, w3 = __ldg(g_dinv + s3) * dn;
        float4 v0 = *(const float4*)(g_h1 + (size_t)s0 * 64 + hl * 4);
        float4 v1 = *(const float4*)(g_h1 + (size_t)s1 * 64 + hl * 4);
        float4 v2 = *(const float4*)(g_h1 + (size_t)s2 * 64 + hl * 4);
        float4 v3 = *(const float4*)(g_h1 + (size_t)s3 * 64 + hl * 4);
        acc.x += v0.x * w0 + v1.x * w1 + v2.x * w2 + v3.x * w3;
        acc.y += v0.y * w0 + v1.y * w1 + v2.y * w2 + v3.y * w3;
        acc.z += v0.z * w0 + v1.z * w1 + v2.z * w2 + v3.z * w3;
        acc.w += v0.w * w0 + v1.w * w1 + v2.w * w2 + v3.w * w3;
    }
    for (; e < deg; e += 2) {
        int s0 = __ldg(bp + e);
        float w0 = __ldg(g_dinv + s0) * dn;
        float4 v0 = *(const float4*)(g_h1 + (size_t)s0 * 64 + hl * 4);
        acc.x += v0.x * w0; acc.y += v0.y * w0;
        acc.z += v0.z * w0; acc.w += v0.w * w0;
    }

    acc.x += __shfl_xor_sync(0xFFFFFFFFu, acc.x, 16);
    acc.y += __shfl_xor_sync(0xFFFFFFFFu, acc.y, 16);
    acc.z += __shfl_xor_sync(0xFFFFFFFFu, acc.z, 16);
    acc.w += __shfl_xor_sync(0xFFFFFFFFu, acc.w, 16);

    if (half == 0) {
        float sl = dn * dn;
        float4 h = *(const float4*)(g_h1 + (size_t)n * 64 + hl * 4);
        float4 bb = *(const float4*)(b1 + hl * 4);
        float4 o;
        o.x = fmaxf(acc.x + h.x * sl + bb.x, 0.f);
        o.y = fmaxf(acc.y + h.y * sl + bb.y, 0.f);
        o.z = fmaxf(acc.z + h.z * sl + bb.z, 0.f);
        o.w = fmaxf(acc.w + h.w * sl + bb.w, 0.f);
        *(float4*)(g_h2 + (size_t)n * 64 + hl * 4) = o;
    }
}

// ---------------- GEMM layer 2: g_h3 = h2 @ W2 (f32x2 packed) ----------------
__global__ __launch_bounds__(256) void gemm2_k(const float* __restrict__ W, int N)
{
    __shared__ __align__(16) float Ws[64 * 40];
    for (int i = threadIdx.x; i < 64 * 40; i += 256) Ws[i] = W[i];
    __syncthreads();

    int r = blockIdx.x * 256 + threadIdx.x;
    if (r >= N) return;

    ull acc[20];
#pragma unroll
    for (int j = 0; j < 20; j++) acc[j] = 0ULL;

    const float4* xr = (const float4*)(g_h2 + (size_t)r * 64);
#pragma unroll 1
    for (int k4 = 0; k4 < 16; k4++) {
        float4 xv = xr[k4];
        ull xa, xb, xc, xd;
        PACK2(xa, xv.x, xv.x); PACK2(xb, xv.y, xv.y);
        PACK2(xc, xv.z, xv.z); PACK2(xd, xv.w, xv.w);
        const ulonglong2* w0 = (const ulonglong2*)(Ws + (k4 * 4 + 0) * 40);
        const ulonglong2* w1 = (const ulonglong2*)(Ws + (k4 * 4 + 1) * 40);
        const ulonglong2* w2 = (const ulonglong2*)(Ws + (k4 * 4 + 2) * 40);
        const ulonglong2* w3 = (const ulonglong2*)(Ws + (k4 * 4 + 3) * 40);
#pragma unroll
        for (int j = 0; j < 10; j++) {
            ulonglong2 a0 = w0[j]; FMA2(acc[2*j], xa, a0.x); FMA2(acc[2*j+1], xa, a0.y);
            ulonglong2 a1 = w1[j]; FMA2(acc[2*j], xb, a1.x); FMA2(acc[2*j+1], xb, a1.y);
            ulonglong2 a2 = w2[j]; FMA2(acc[2*j], xc, a2.x); FMA2(acc[2*j+1], xc, a2.y);
            ulonglong2 a3 = w3[j]; FMA2(acc[2*j], xd, a3.x); FMA2(acc[2*j+1], xd, a3.y);
        }
    }

    ulonglong2* Hp = (ulonglong2*)(g_h3 + (size_t)r * 40);
#pragma unroll
    for (int j = 0; j < 10; j++) {
        ulonglong2 v; v.x = acc[2*j]; v.y = acc[2*j+1];
        Hp[j] = v;
    }
}

// -------- gather layer 2 + bias + log_softmax --------
// one warp per node; lanes 0..19 own features [2*lane, 2*lane+1] of 40
__global__ __launch_bounds__(256) void gather2_k(float* __restrict__ out,
                                                 const float* __restrict__ b2, int N)
{
    int wid = (blockIdx.x * 256 + threadIdx.x) >> 5;
    int lane = threadIdx.x & 31;
    if (wid >= N) return;
    int n = wid;
    bool act = lane < 20;
    int fo = act ? lane * 2 : 0;

    int deg = min(g_cnt[n], CAP);
    const int* bp = g_bkt + (size_t)n * CAP;
    float dn = g_dinv[n];

    float2 a0 = make_float2(0.f, 0.f), a1 = make_float2(0.f, 0.f);
    float2 a2 = make_float2(0.f, 0.f), a3 = make_float2(0.f, 0.f);
    int e = 0;
    for (; e + 3 < deg; e += 4) {
        int s0 = __ldg(bp + e),     s1 = __ldg(bp + e + 1);
        int s2 = __ldg(bp + e + 2), s3 = __ldg(bp + e + 3);
        float w0 = __ldg(g_dinv + s0) * dn, w1 = __ldg(g_dinv + s1) * dn;
        float w2 = __ldg(g_dinv + s2) * dn, w3 = __ldg(g_dinv + s3) * dn;
        float2 v0 = *(const float2*)(g_h3 + (size_t)s0 * 40 + fo);
        float2 v1 = *(const float2*)(g_h3 + (size_t)s1 * 40 + fo);
        float2 v2 = *(const float2*)(g_h3 + (size_t)s2 * 40 + fo);
        float2 v3 = *(const float2*)(g_h3 + (size_t)s3 * 40 + fo);
        a0.x += v0.x * w0; a0.y += v0.y * w0;
        a1.x += v1.x * w1; a1.y += v1.y * w1;
        a2.x += v2.x * w2; a2.y += v2.y * w2;
        a3.x += v3.x * w3; a3.y += v3.y * w3;
    }
    for (; e < deg; e++) {
        int s0 = __ldg(bp + e);
        float w0 = __ldg(g_dinv + s0) * dn;
        float2 v0 = *(const float2*)(g_h3 + (size_t)s0 * 40 + fo);
        a0.x += v0.x * w0; a0.y += v0.y * w0;
    }

    float sl = dn * dn;
    float2 h = *(const float2*)(g_h3 + (size_t)n * 40 + fo);
    float2 bb = *(const float2*)(b2 + fo);
    float vx = a0.x + a1.x + a2.x + a3.x + h.x * sl + bb.x;
    float vy = a0.y + a1.y + a2.y + a3.y + h.y * sl + bb.y;

    float m = act ? fmaxf(vx, vy) : -3.0e38f;
#pragma unroll
    for (int o = 16; o > 0; o >>= 1) m = fmaxf(m, __shfl_xor_sync(0xFFFFFFFFu, m, o));
    float s = act ? (expf(vx - m) + expf(vy - m)) : 0.f;
#pragma unroll
    for (int o = 16; o > 0; o >>= 1) s += __shfl_xor_sync(0xFFFFFFFFu, s, o);
    float lse = m + logf(s);

    if (act)
        *(float2*)(out + (size_t)n * 40 + fo) = make_float2(vx - lse, vy - lse);
}

extern "C" void kernel_launch(void* const* d_in, const int* in_sizes, int n_in,
                              void* d_out, int out_size)
{
    const float* x  = (const float*)d_in[0];
    const int*   ei = (const int*)d_in[1];      // int32 (JAX x64 disabled)
    const float* W1 = (const float*)d_in[2];
    const float* b1 = (const float*)d_in[3];
    const float* W2 = (const float*)d_in[4];
    const float* b2 = (const float*)d_in[5];
    float* out = (float*)d_out;

    int N = in_sizes[0] / 128;
    int E = in_sizes[1] / 2;
    const int T = 256;

    // bucket build
    void* cnt_ptr = 0;
    cudaGetSymbolAddress(&cnt_ptr, g_cnt);
    cudaMemsetAsync(cnt_ptr, 0, (size_t)N * sizeof(int));
    bucket_k<<<(E + T - 1) / T, T>>>(ei, E, N);
    dinv_k<<<(N + T - 1) / T, T>>>(N);

    // layer 1
    gemm1_k<<<(N + T - 1) / T, T>>>(x, W1, N);
    gather1_k<<<(N * 32 + T - 1) / T, T>>>(b1, N);

    // layer 2
    gemm2_k<<<(N + T - 1) / T, T>>>(W2, N);
    gather2_k<<<(N * 32 + T - 1) / T, T>>>(out, b2, N);
}